// round 13
// baseline (speedup 1.0000x reference)
#include <cuda_runtime.h>
#include <cuda_fp16.h>
#include <cstdint>

// ============================================================================
// Binarized-weight 3x3 conv, stride 1, pad 1, via implicit GEMM on HMMA
// (mma.sync m16n8k16 fp16 -> fp32 accum; arch-neutral PTX at compute_103).
// x: (32,128,64,64) f32 NCHW ; w: (256,128,3,3) f32 OIHW -> sign(w) ; out f32.
//
// Tile = 2 output rows x 64 cols (128 positions) in padded 66x66 space.
// Single-pass fp16 (~2e-4 rel_err). R13: one CTA handles BOTH 128-co halves
// (A halo loaded once, reused); epilogue staged through the B-buffer region
// in two 64-co chunks; prep_x vectorized (float4 loads).
// ============================================================================

#define NPOS_STRIDE 4736ull   // 128 guard + 66*66 + tail guard
#define POS_BASE    128
#define N_TILES     32        // 32 output-row-pairs
#define A_ROWS      264       // rows [base-67, base+196] around the tile

// -------- scratch (zero-initialized device globals; guards stay 0) ----------
__device__ __half g_xh[32ull * NPOS_STRIDE * 128];
__device__ __half g_wb[2 * 9 * 256 * 64];   // [chunk*9+tap][co][ci64]

// ---------------------------- helpers ---------------------------------------
__device__ __forceinline__ uint32_t smem_u32(const void* p) {
    uint32_t a;
    asm("{ .reg .u64 t; cvta.to.shared.u64 t, %1; cvt.u32.u64 %0, t; }"
        : "=r"(a) : "l"(p));
    return a;
}

#define CP_ASYNC16(dst_u32, src_ptr) \
    asm volatile("cp.async.cg.shared.global [%0], [%1], 16;" \
                 :: "r"(dst_u32), "l"(src_ptr))
#define CP_COMMIT() asm volatile("cp.async.commit_group;" ::: "memory")
#define CP_WAIT0()  asm volatile("cp.async.wait_group 0;" ::: "memory")

__device__ __forceinline__ void ldsm_x4(uint32_t& r0, uint32_t& r1,
                                        uint32_t& r2, uint32_t& r3,
                                        uint32_t addr) {
    asm volatile("ldmatrix.sync.aligned.m8n8.x4.shared.b16 {%0,%1,%2,%3}, [%4];"
                 : "=r"(r0), "=r"(r1), "=r"(r2), "=r"(r3) : "r"(addr));
}

__device__ __forceinline__ void mma_f16(float* c, const uint32_t* a,
                                        uint32_t b0, uint32_t b1) {
    asm volatile(
        "mma.sync.aligned.m16n8k16.row.col.f32.f16.f16.f32 "
        "{%0,%1,%2,%3}, {%4,%5,%6,%7}, {%8,%9}, {%0,%1,%2,%3};"
        : "+f"(c[0]), "+f"(c[1]), "+f"(c[2]), "+f"(c[3])
        : "r"(a[0]), "r"(a[1]), "r"(a[2]), "r"(a[3]), "r"(b0), "r"(b1));
}

// ----------------- merged pre-kernel: pad/transpose x + weights --------------
// blocks [0, 2048): x prep (h = b & 63, n = b >> 6), float4 loads, 16B stores
// blocks [2048, 2304): w prep, one block per co, coalesced plane writes
__global__ void __launch_bounds__(256) prep_all(const float* __restrict__ x,
                                                const float* __restrict__ w) {
    const int b = blockIdx.x;
    const int t = threadIdx.x;
    if (b < 2048) {
        __shared__ float st[64 * 132];     // [w][ci], stride 132 (16B-aligned)
        const int h = b & 63, n = b >> 6;
        // phase 1: LDG.128 along w; transpose into smem
        const float4* xv = (const float4*)(x + ((size_t)n * 128) * 4096 + h * 64);
        for (int idx = t; idx < 2048; idx += 256) {
            const int ci = idx >> 4, w4 = idx & 15;
            const float4 v = xv[(size_t)ci * 1024 + w4];
            st[(w4 * 4 + 0) * 132 + ci] = v.x;
            st[(w4 * 4 + 1) * 132 + ci] = v.y;
            st[(w4 * 4 + 2) * 132 + ci] = v.z;
            st[(w4 * 4 + 3) * 132 + ci] = v.w;
        }
        __syncthreads();
        // phase 2: convert + 16B stores, ci-contiguous
        const size_t rowbase = (size_t)n * NPOS_STRIDE + POS_BASE +
                               (size_t)(h + 1) * 66 + 1;
        for (int idx2 = t; idx2 < 1024; idx2 += 256) {
            const int ww = idx2 >> 4, ci0 = (idx2 & 15) << 3;
            const float* src = &st[ww * 132 + ci0];
            __half2 hv[4];
#pragma unroll
            for (int k = 0; k < 4; k++)
                hv[k] = __floats2half2_rn(src[2 * k], src[2 * k + 1]);
            *(uint4*)(g_xh + (rowbase + ww) * 128 + ci0) = *(uint4*)hv;
        }
    } else {
        const int co = b - 2048;
        __shared__ __half ss[1152];        // [ci][tap]
        for (int i = t; i < 1152; i += 256) {
            float v = w[co * 1152 + i];
            ss[i] = __float2half_rn((v > 0.f) ? 1.f : ((v < 0.f) ? -1.f : 0.f));
        }
        __syncthreads();
        for (int i2 = t; i2 < 1152; i2 += 256) {
            const int plane = i2 >> 6, ci = i2 & 63;
            const int chunk = plane / 9, tap = plane - chunk * 9;
            g_wb[(plane << 14) + (co << 6) + ci] =
                ss[((chunk << 6) + ci) * 9 + tap];
        }
    }
}

// ------------------------------- main kernel ---------------------------------
// dynamic smem layout (bytes):
//   A  : [0,     67584)   264 rows x 256B (128 ci), swizzled; loaded ONCE
//   B0 : [67584, 84480)   16KB tile + 512 pad (double-buffered)
//   B1 : [84480, 101376)
//   D (epilogue): 64co x 132 f32 chunk = 33792B = exactly B0+B1 region
#define SM_A     0
#define SM_B0    67584
#define SM_B1    84480
#define SM_TOTAL 101376

__global__ void __launch_bounds__(256, 2)
bconv_hmma(float* __restrict__ out) {
    extern __shared__ char sm[];
    const uint32_t smb = smem_u32(sm);

    const int t    = threadIdx.x;
    const int wid  = t >> 5;
    const int lane = t & 31;
    const int n    = blockIdx.y;
    const int tile = blockIdx.x;           // output rows (2*tile, 2*tile+1)

    const int mw = wid & 1;                // 2 m-halves of 64 positions
    const int nw = wid >> 1;               // 4 n-quarters of 32 co

    // lane-invariant ldmatrix offsets
    const int q  = lane >> 3;
    const int rA = (lane & 7) + ((q & 1) << 3);     // A row-in-tile
    const int cA = q >> 1;                          // A k-half (16B unit)
    const int rB = (lane & 7) + ((lane >> 4) << 3); // B row-in-pair
    const int cB = q & 1;                           // B k-half

    const uint32_t bRowOff = (uint32_t)(nw * 32 + rB) * 128;
    const uint32_t bXorM   = (uint32_t)(rB & 7);

    // halo row 0 = padded position 132*tile (tile base = 132*tile + 67)
    const size_t xrow0 = ((size_t)n * NPOS_STRIDE + POS_BASE + 132 * tile) * 128;

    // ---- A halo prologue (once, shared by both co-halves) ----
    for (int i = t; i < A_ROWS * 16; i += 256) {
        const int r = i >> 4, j = i & 15;
        const size_t gsrc = xrow0 + (size_t)r * 128 + (j << 3);
        const uint32_t doff = (uint32_t)(r * 256 + ((j ^ (r & 7)) << 4));
        CP_ASYNC16(smb + SM_A + doff, g_xh + gsrc);
    }
    CP_COMMIT();

#pragma unroll 1
    for (int coH = 0; coH < 2; coH++) {
        const __half* wbase = g_wb + (coH << 13);

        // prefetch B(iter 0) for this half
        for (int i = t; i < 1024; i += 256) {
            const int r = i >> 3, j = i & 7;
            const uint32_t doff = (uint32_t)(r * 128 + ((j ^ (r & 7)) << 4));
            CP_ASYNC16(smb + SM_B0 + doff, wbase + (i << 3));
        }
        CP_COMMIT();

        float acc[4][4][4];
#pragma unroll
        for (int i = 0; i < 4; i++)
#pragma unroll
            for (int j = 0; j < 4; j++)
#pragma unroll
                for (int k = 0; k < 4; k++) acc[i][j][k] = 0.f;

#pragma unroll 1
        for (int iter = 0; iter < 18; ++iter) {
            const int chunk = iter / 9;
            const int tap   = iter - chunk * 9;

            CP_WAIT0();            // B(iter) landed (coH=0, iter 0: + A halo)
            __syncthreads();       // frees the other B buffer for prefetch

            if (iter < 17) {       // prefetch next iter's B
                const __half* src = wbase + ((iter + 1) << 14);
                const uint32_t bdst = smb + (((iter + 1) & 1) ? SM_B1 : SM_B0);
                for (int i = t; i < 1024; i += 256) {
                    const int r = i >> 3, j = i & 7;
                    const uint32_t doff =
                        (uint32_t)(r * 128 + ((j ^ (r & 7)) << 4));
                    CP_ASYNC16(bdst + doff, src + (i << 3));
                }
                CP_COMMIT();
            }

            // ---- compute tap/chunk ----
            const int s = (tap / 3 - 1) * 66 + (tap % 3 - 1);
            const int aRow0 = mw * 66 + s + 67 + rA;
            const uint32_t aBase = smb + SM_A + (uint32_t)aRow0 * 256;
            const uint32_t aXorM = (uint32_t)(aRow0 & 7);
            const uint32_t bBase = smb + ((iter & 1) ? SM_B1 : SM_B0) + bRowOff;
            const int cbase = chunk << 3;

#pragma unroll
            for (int ks = 0; ks < 4; ks++) {
                uint32_t bf[4][2];
#pragma unroll
                for (int pr = 0; pr < 2; pr++) {
                    const uint32_t addr = bBase + pr * 2048 +
                        (((uint32_t)(2 * ks + cB) ^ bXorM) << 4);
                    ldsm_x4(bf[pr * 2][0], bf[pr * 2][1],
                            bf[pr * 2 + 1][0], bf[pr * 2 + 1][1], addr);
                }
                uint32_t af[4][4];
#pragma unroll
                for (int mt = 0; mt < 4; mt++) {
                    const uint32_t addr = aBase + mt * 4096 +
                        (((uint32_t)(cbase + 2 * ks + cA) ^ aXorM) << 4);
                    ldsm_x4(af[mt][0], af[mt][1], af[mt][2], af[mt][3], addr);
                }
#pragma unroll
                for (int mt = 0; mt < 4; mt++)
#pragma unroll
                    for (int nt = 0; nt < 4; nt++)
                        mma_f16(acc[mt][nt], af[mt], bf[nt][0], bf[nt][1]);
            }
        }

        // ---- epilogue for this half: two 64-co chunks through B region ----
        __syncthreads();           // all B reads done; B region becomes D
        float* D = (float*)(sm + SM_B0);
        const int gRow = lane >> 2;
        const int gCol = (lane & 3) * 2;

#pragma unroll 1
        for (int cg = 0; cg < 2; cg++) {
            if ((nw >> 1) == cg) {
                const int nwL = nw & 1;
#pragma unroll
                for (int mt = 0; mt < 4; mt++) {
#pragma unroll
                    for (int nt = 0; nt < 4; nt++) {
                        const int pl  = mw * 64 + mt * 16 + gRow;
                        const int col = nwL * 32 + nt * 8 + gCol;
                        D[col * 132 + pl]           = acc[mt][nt][0];
                        D[(col + 1) * 132 + pl]     = acc[mt][nt][1];
                        D[col * 132 + pl + 8]       = acc[mt][nt][2];
                        D[(col + 1) * 132 + pl + 8] = acc[mt][nt][3];
                    }
                }
            }
            __syncthreads();
            // store chunk: 64 co x 128 positions, coalesced
            for (int i = t; i < 64 * 128; i += 256) {
                const int co_l = i >> 7, p_l = i & 127;
                const int h = 2 * tile + (p_l >> 6);
                out[(((size_t)n * 256 + coH * 128 + cg * 64 + co_l) << 12) +
                    (h << 6) + (p_l & 63)] = D[co_l * 132 + p_l];
            }
            __syncthreads();
        }
    }
}

// ------------------------------- launcher ------------------------------------
extern "C" void kernel_launch(void* const* d_in, const int* in_sizes, int n_in,
                              void* d_out, int out_size) {
    const float* x = (const float*)d_in[0];
    const float* w = (const float*)d_in[1];
    float* out = (float*)d_out;

    cudaFuncSetAttribute(bconv_hmma, cudaFuncAttributeMaxDynamicSharedMemorySize,
                         SM_TOTAL);

    prep_all<<<2304, 256>>>(x, w);
    bconv_hmma<<<dim3(N_TILES, 32), 256, SM_TOTAL>>>(out);
}

// round 14
// speedup vs baseline: 1.1386x; 1.1386x over previous
#include <cuda_runtime.h>
#include <cuda_fp16.h>
#include <cstdint>

// ============================================================================
// Binarized-weight 3x3 conv, stride 1, pad 1, via implicit GEMM on HMMA
// (mma.sync m16n8k16 fp16 -> fp32 accum; arch-neutral PTX at compute_103).
// x: (32,128,64,64) f32 NCHW ; w: (256,128,3,3) f32 OIHW -> sign(w) ; out f32.
//
// Tile = 2 output rows x 64 cols (128 positions) in padded 66x66 space.
// Single-pass fp16 (~2e-4 rel_err). A halo loaded once per CTA; B double-
// buffered cp.async. R14: per-iter CTA __syncthreads replaced by per-pair
// named barriers (each 2-warp pair owns + prefetches its own 32-row B quarter),
// decoupling the 4 pairs' pipeline drains.
// ============================================================================

#define NPOS_STRIDE 4736ull   // 128 guard + 66*66 + tail guard
#define POS_BASE    128
#define N_TILES     32        // 32 output-row-pairs
#define A_ROWS      264       // rows [base-67, base+196] around the tile

// -------- scratch (zero-initialized device globals; guards stay 0) ----------
__device__ __half g_xh[32ull * NPOS_STRIDE * 128];
__device__ __half g_wb[2 * 9 * 256 * 64];   // [chunk*9+tap][co][ci64]

// ---------------------------- helpers ---------------------------------------
__device__ __forceinline__ uint32_t smem_u32(const void* p) {
    uint32_t a;
    asm("{ .reg .u64 t; cvta.to.shared.u64 t, %1; cvt.u32.u64 %0, t; }"
        : "=r"(a) : "l"(p));
    return a;
}

#define CP_ASYNC16(dst_u32, src_ptr) \
    asm volatile("cp.async.cg.shared.global [%0], [%1], 16;" \
                 :: "r"(dst_u32), "l"(src_ptr))
#define CP_COMMIT() asm volatile("cp.async.commit_group;" ::: "memory")
#define CP_WAIT0()  asm volatile("cp.async.wait_group 0;" ::: "memory")
#define PAIR_BAR(id) \
    asm volatile("bar.sync %0, 64;" :: "r"(id) : "memory")

__device__ __forceinline__ void ldsm_x4(uint32_t& r0, uint32_t& r1,
                                        uint32_t& r2, uint32_t& r3,
                                        uint32_t addr) {
    asm volatile("ldmatrix.sync.aligned.m8n8.x4.shared.b16 {%0,%1,%2,%3}, [%4];"
                 : "=r"(r0), "=r"(r1), "=r"(r2), "=r"(r3) : "r"(addr));
}

__device__ __forceinline__ void mma_f16(float* c, const uint32_t* a,
                                        uint32_t b0, uint32_t b1) {
    asm volatile(
        "mma.sync.aligned.m16n8k16.row.col.f32.f16.f16.f32 "
        "{%0,%1,%2,%3}, {%4,%5,%6,%7}, {%8,%9}, {%0,%1,%2,%3};"
        : "+f"(c[0]), "+f"(c[1]), "+f"(c[2]), "+f"(c[3])
        : "r"(a[0]), "r"(a[1]), "r"(a[2]), "r"(a[3]), "r"(b0), "r"(b1));
}

// ----------------- merged pre-kernel: pad/transpose x + weights --------------
// blocks [0, 2048): x prep (h = b & 63, n = b >> 6), vectorized 16B stores
// blocks [2048, 2304): w prep, one block per co, coalesced plane writes
__global__ void __launch_bounds__(256) prep_all(const float* __restrict__ x,
                                                const float* __restrict__ w) {
    const int b = blockIdx.x;
    const int t = threadIdx.x;
    if (b < 2048) {
        __shared__ float st[64 * 129];
        const int h = b & 63, n = b >> 6;
        for (int idx = t; idx < 8192; idx += 256) {
            int ci = idx >> 6, ww = idx & 63;
            st[ww * 129 + ci] = x[(((size_t)n * 128 + ci) * 64 + h) * 64 + ww];
        }
        __syncthreads();
        const size_t rowbase = (size_t)n * NPOS_STRIDE + POS_BASE +
                               (size_t)(h + 1) * 66 + 1;
        for (int idx2 = t; idx2 < 1024; idx2 += 256) {
            const int ww = idx2 >> 4, ci0 = (idx2 & 15) << 3;
            const float* src = &st[ww * 129 + ci0];
            __half2 hv[4];
#pragma unroll
            for (int k = 0; k < 4; k++)
                hv[k] = __floats2half2_rn(src[2 * k], src[2 * k + 1]);
            *(uint4*)(g_xh + (rowbase + ww) * 128 + ci0) = *(uint4*)hv;
        }
    } else {
        const int co = b - 2048;
        __shared__ __half ss[1152];        // [ci][tap]
        for (int i = t; i < 1152; i += 256) {
            float v = w[co * 1152 + i];
            ss[i] = __float2half_rn((v > 0.f) ? 1.f : ((v < 0.f) ? -1.f : 0.f));
        }
        __syncthreads();
        for (int i2 = t; i2 < 1152; i2 += 256) {
            const int plane = i2 >> 6, ci = i2 & 63;
            const int chunk = plane / 9, tap = plane - chunk * 9;
            g_wb[(plane << 14) + (co << 6) + ci] =
                ss[((chunk << 6) + ci) * 9 + tap];
        }
    }
}

// ------------------------------- main kernel ---------------------------------
// dynamic smem layout (bytes):
//   A  : [0,     67584)   264 rows x 256B (128 ci), swizzled; loaded ONCE
//   B0 : [67584, 83968)   128 rows x 128B (64 ci), swizzled (double-buffered)
//   B1 : [83968, 100352)
//   D (epilogue, reuses A): 128co x 132 floats = 67584B
#define SM_A     0
#define SM_B0    67584
#define SM_B1    83968
#define SM_TOTAL 100352

__global__ void __launch_bounds__(256, 2)
bconv_hmma(float* __restrict__ out) {
    extern __shared__ char sm[];
    const uint32_t smb = smem_u32(sm);

    const int t    = threadIdx.x;
    const int wid  = t >> 5;
    const int lane = t & 31;
    const int n    = blockIdx.z;
    const int coB  = blockIdx.y;           // 0/1 -> co block of 128
    const int tile = blockIdx.x;           // output rows (2*tile, 2*tile+1)

    const int mw = wid & 1;                // 2 m-halves of 64 positions
    const int nw = wid >> 1;               // 4 n-quarters of 32 co
    const int pt = t & 63;                 // thread id within the nw-pair

    // lane-invariant ldmatrix offsets
    const int q  = lane >> 3;
    const int rA = (lane & 7) + ((q & 1) << 3);     // A row-in-tile
    const int cA = q >> 1;                          // A k-half (16B unit)
    const int rB = (lane & 7) + ((lane >> 4) << 3); // B row-in-pair
    const int cB = q & 1;                           // B k-half

    const uint32_t bRowOff = (uint32_t)(nw * 32 + rB) * 128;
    const uint32_t bXorM   = (uint32_t)(rB & 7);

    float acc[4][4][4];
#pragma unroll
    for (int i = 0; i < 4; i++)
#pragma unroll
        for (int j = 0; j < 4; j++)
#pragma unroll
            for (int k = 0; k < 4; k++) acc[i][j][k] = 0.f;

    // halo row 0 = padded position 132*tile (tile base = 132*tile + 67)
    const size_t xrow0 = ((size_t)n * NPOS_STRIDE + POS_BASE + 132 * tile) * 128;
    const __half* wbase = g_wb + (coB << 13);   // co block offset

    // ---- prologue ----
    // B(iter 0): each pair loads ONLY its own 32-row quarter (4 x 16B / thread)
#pragma unroll
    for (int k = 0; k < 4; k++) {
        const int u = pt + (k << 6);               // 0..255 within quarter
        const int r = (nw << 5) + (u >> 3), j = u & 7;
        const uint32_t doff = (uint32_t)(r * 128 + ((j ^ (r & 7)) << 4));
        CP_ASYNC16(smb + SM_B0 + doff, wbase + (r << 6) + (j << 3));
    }
    CP_COMMIT();
    // A halo: 264 rows x 256B, all threads
    for (int i = t; i < A_ROWS * 16; i += 256) {
        const int r = i >> 4, j = i & 15;
        const size_t gsrc = xrow0 + (size_t)r * 128 + (j << 3);
        const uint32_t doff = (uint32_t)(r * 256 + ((j ^ (r & 7)) << 4));
        CP_ASYNC16(smb + SM_A + doff, g_xh + gsrc);
    }
    CP_COMMIT();
    CP_WAIT0();
    __syncthreads();           // A + B0 visible to all warps

#pragma unroll 1
    for (int iter = 0; iter < 18; ++iter) {
        const int chunk = iter / 9;
        const int tap   = iter - chunk * 9;

        // own B(iter)-quarter writes landed (committed previous iter)
        CP_WAIT0();
        // partner's writes visible + partner done computing iter-1
        PAIR_BAR(1 + nw);

        if (iter < 17) {       // prefetch own quarter of B(iter+1)
            const __half* src = wbase + ((iter + 1) << 14);
            const uint32_t bdst = smb + (((iter + 1) & 1) ? SM_B1 : SM_B0);
#pragma unroll
            for (int k = 0; k < 4; k++) {
                const int u = pt + (k << 6);
                const int r = (nw << 5) + (u >> 3), j = u & 7;
                const uint32_t doff = (uint32_t)(r * 128 + ((j ^ (r & 7)) << 4));
                CP_ASYNC16(bdst + doff, src + (r << 6) + (j << 3));
            }
            CP_COMMIT();
        }

        // ---- compute tap/chunk ----
        const int s = (tap / 3 - 1) * 66 + (tap % 3 - 1);
        const int aRow0 = mw * 66 + s + 67 + rA;
        const uint32_t aBase = smb + SM_A + (uint32_t)aRow0 * 256;
        const uint32_t aXorM = (uint32_t)(aRow0 & 7);
        const uint32_t bBase = smb + ((iter & 1) ? SM_B1 : SM_B0) + bRowOff;
        const int cbase = chunk << 3;

#pragma unroll
        for (int ks = 0; ks < 4; ks++) {
            uint32_t bf[4][2];
#pragma unroll
            for (int pr = 0; pr < 2; pr++) {
                const uint32_t addr = bBase + pr * 2048 +
                    (((uint32_t)(2 * ks + cB) ^ bXorM) << 4);
                ldsm_x4(bf[pr * 2][0], bf[pr * 2][1],
                        bf[pr * 2 + 1][0], bf[pr * 2 + 1][1], addr);
            }
            uint32_t af[4][4];
#pragma unroll
            for (int mt = 0; mt < 4; mt++) {
                const uint32_t addr = aBase + mt * 4096 +
                    (((uint32_t)(cbase + 2 * ks + cA) ^ aXorM) << 4);
                ldsm_x4(af[mt][0], af[mt][1], af[mt][2], af[mt][3], addr);
            }
#pragma unroll
            for (int mt = 0; mt < 4; mt++)
#pragma unroll
                for (int nt = 0; nt < 4; nt++)
                    mma_f16(acc[mt][nt], af[mt], bf[nt][0], bf[nt][1]);
        }
    }

    // ---- epilogue: acc -> smem D [co][132] -> coalesced gmem (no masking) ----
    __syncthreads();           // all pairs done; A region becomes D
    float* D = (float*)sm;
    const int gRow = lane >> 2;
    const int gCol = (lane & 3) * 2;
#pragma unroll
    for (int mt = 0; mt < 4; mt++) {
#pragma unroll
        for (int nt = 0; nt < 4; nt++) {
            const int pl  = mw * 64 + mt * 16 + gRow;
            const int col = nw * 32 + nt * 8 + gCol;
            D[col * 132 + pl]           = acc[mt][nt][0];
            D[(col + 1) * 132 + pl]     = acc[mt][nt][1];
            D[col * 132 + pl + 8]       = acc[mt][nt][2];
            D[(col + 1) * 132 + pl + 8] = acc[mt][nt][3];
        }
    }
    __syncthreads();

    // p_l: 0..63 -> output row 2*tile, 64..127 -> 2*tile+1; col = p_l & 63
    for (int i = t; i < 128 * 128; i += 256) {
        const int co_l = i >> 7, p_l = i & 127;
        const int h = 2 * tile + (p_l >> 6);
        out[(((size_t)n * 256 + coB * 128 + co_l) << 12) + (h << 6) + (p_l & 63)]
            = D[co_l * 132 + p_l];
    }
}

// ------------------------------- launcher ------------------------------------
extern "C" void kernel_launch(void* const* d_in, const int* in_sizes, int n_in,
                              void* d_out, int out_size) {
    const float* x = (const float*)d_in[0];
    const float* w = (const float*)d_in[1];
    float* out = (float*)d_out;

    cudaFuncSetAttribute(bconv_hmma, cudaFuncAttributeMaxDynamicSharedMemorySize,
                         SM_TOTAL);

    prep_all<<<2304, 256>>>(x, w);
    bconv_hmma<<<dim3(N_TILES, 2, 32), 256, SM_TOTAL>>>(out);
}

// round 15
// speedup vs baseline: 1.1584x; 1.0174x over previous
#include <cuda_runtime.h>
#include <cuda_fp16.h>
#include <cstdint>

// ============================================================================
// Binarized-weight 3x3 conv, stride 1, pad 1, via implicit GEMM on HMMA
// (mma.sync m16n8k16 fp16 -> fp32 accum; arch-neutral PTX at compute_103).
// x: (32,128,64,64) f32 NCHW ; w: (256,128,3,3) f32 OIHW -> sign(w) ; out f32.
//
// Tile = 2 output rows x 64 cols (128 positions) in padded 66x66 space.
// Single-pass fp16 (~2e-4 rel_err). A halo loaded once per CTA; B double-
// buffered cp.async with per-pair named barriers (R14 mainloop, frozen).
// R15: faster prep_x (float4 loads, from R13) + float4 epilogue stores.
// ============================================================================

#define NPOS_STRIDE 4736ull   // 128 guard + 66*66 + tail guard
#define POS_BASE    128
#define N_TILES     32        // 32 output-row-pairs
#define A_ROWS      264       // rows [base-67, base+196] around the tile

// -------- scratch (zero-initialized device globals; guards stay 0) ----------
__device__ __half g_xh[32ull * NPOS_STRIDE * 128];
__device__ __half g_wb[2 * 9 * 256 * 64];   // [chunk*9+tap][co][ci64]

// ---------------------------- helpers ---------------------------------------
__device__ __forceinline__ uint32_t smem_u32(const void* p) {
    uint32_t a;
    asm("{ .reg .u64 t; cvta.to.shared.u64 t, %1; cvt.u32.u64 %0, t; }"
        : "=r"(a) : "l"(p));
    return a;
}

#define CP_ASYNC16(dst_u32, src_ptr) \
    asm volatile("cp.async.cg.shared.global [%0], [%1], 16;" \
                 :: "r"(dst_u32), "l"(src_ptr))
#define CP_COMMIT() asm volatile("cp.async.commit_group;" ::: "memory")
#define CP_WAIT0()  asm volatile("cp.async.wait_group 0;" ::: "memory")
#define PAIR_BAR(id) \
    asm volatile("bar.sync %0, 64;" :: "r"(id) : "memory")

__device__ __forceinline__ void ldsm_x4(uint32_t& r0, uint32_t& r1,
                                        uint32_t& r2, uint32_t& r3,
                                        uint32_t addr) {
    asm volatile("ldmatrix.sync.aligned.m8n8.x4.shared.b16 {%0,%1,%2,%3}, [%4];"
                 : "=r"(r0), "=r"(r1), "=r"(r2), "=r"(r3) : "r"(addr));
}

__device__ __forceinline__ void mma_f16(float* c, const uint32_t* a,
                                        uint32_t b0, uint32_t b1) {
    asm volatile(
        "mma.sync.aligned.m16n8k16.row.col.f32.f16.f16.f32 "
        "{%0,%1,%2,%3}, {%4,%5,%6,%7}, {%8,%9}, {%0,%1,%2,%3};"
        : "+f"(c[0]), "+f"(c[1]), "+f"(c[2]), "+f"(c[3])
        : "r"(a[0]), "r"(a[1]), "r"(a[2]), "r"(a[3]), "r"(b0), "r"(b1));
}

// ----------------- merged pre-kernel: pad/transpose x + weights --------------
// blocks [0, 2048): x prep (h = b & 63, n = b >> 6), float4 loads, 16B stores
// blocks [2048, 2304): w prep, one block per co, coalesced plane writes
__global__ void __launch_bounds__(256) prep_all(const float* __restrict__ x,
                                                const float* __restrict__ w) {
    const int b = blockIdx.x;
    const int t = threadIdx.x;
    if (b < 2048) {
        __shared__ float st[64 * 132];     // [w][ci], stride 132 (16B-aligned)
        const int h = b & 63, n = b >> 6;
        // phase 1: LDG.128 along w; transpose into smem
        const float4* xv = (const float4*)(x + ((size_t)n * 128) * 4096 + h * 64);
        for (int idx = t; idx < 2048; idx += 256) {
            const int ci = idx >> 4, w4 = idx & 15;
            const float4 v = xv[(size_t)ci * 1024 + w4];
            st[(w4 * 4 + 0) * 132 + ci] = v.x;
            st[(w4 * 4 + 1) * 132 + ci] = v.y;
            st[(w4 * 4 + 2) * 132 + ci] = v.z;
            st[(w4 * 4 + 3) * 132 + ci] = v.w;
        }
        __syncthreads();
        // phase 2: convert + 16B stores, ci-contiguous
        const size_t rowbase = (size_t)n * NPOS_STRIDE + POS_BASE +
                               (size_t)(h + 1) * 66 + 1;
        for (int idx2 = t; idx2 < 1024; idx2 += 256) {
            const int ww = idx2 >> 4, ci0 = (idx2 & 15) << 3;
            const float* src = &st[ww * 132 + ci0];
            __half2 hv[4];
#pragma unroll
            for (int k = 0; k < 4; k++)
                hv[k] = __floats2half2_rn(src[2 * k], src[2 * k + 1]);
            *(uint4*)(g_xh + (rowbase + ww) * 128 + ci0) = *(uint4*)hv;
        }
    } else {
        const int co = b - 2048;
        __shared__ __half ss[1152];        // [ci][tap]
        for (int i = t; i < 1152; i += 256) {
            float v = w[co * 1152 + i];
            ss[i] = __float2half_rn((v > 0.f) ? 1.f : ((v < 0.f) ? -1.f : 0.f));
        }
        __syncthreads();
        for (int i2 = t; i2 < 1152; i2 += 256) {
            const int plane = i2 >> 6, ci = i2 & 63;
            const int chunk = plane / 9, tap = plane - chunk * 9;
            g_wb[(plane << 14) + (co << 6) + ci] =
                ss[((chunk << 6) + ci) * 9 + tap];
        }
    }
}

// ------------------------------- main kernel ---------------------------------
// dynamic smem layout (bytes):
//   A  : [0,     67584)   264 rows x 256B (128 ci), swizzled; loaded ONCE
//   B0 : [67584, 83968)   128 rows x 128B (64 ci), swizzled (double-buffered)
//   B1 : [83968, 100352)
//   D (epilogue, reuses A): 128co x 132 floats = 67584B
#define SM_A     0
#define SM_B0    67584
#define SM_B1    83968
#define SM_TOTAL 100352

__global__ void __launch_bounds__(256, 2)
bconv_hmma(float* __restrict__ out) {
    extern __shared__ char sm[];
    const uint32_t smb = smem_u32(sm);

    const int t    = threadIdx.x;
    const int wid  = t >> 5;
    const int lane = t & 31;
    const int n    = blockIdx.z;
    const int coB  = blockIdx.y;           // 0/1 -> co block of 128
    const int tile = blockIdx.x;           // output rows (2*tile, 2*tile+1)

    const int mw = wid & 1;                // 2 m-halves of 64 positions
    const int nw = wid >> 1;               // 4 n-quarters of 32 co
    const int pt = t & 63;                 // thread id within the nw-pair

    // lane-invariant ldmatrix offsets
    const int q  = lane >> 3;
    const int rA = (lane & 7) + ((q & 1) << 3);     // A row-in-tile
    const int cA = q >> 1;                          // A k-half (16B unit)
    const int rB = (lane & 7) + ((lane >> 4) << 3); // B row-in-pair
    const int cB = q & 1;                           // B k-half

    const uint32_t bRowOff = (uint32_t)(nw * 32 + rB) * 128;
    const uint32_t bXorM   = (uint32_t)(rB & 7);

    float acc[4][4][4];
#pragma unroll
    for (int i = 0; i < 4; i++)
#pragma unroll
        for (int j = 0; j < 4; j++)
#pragma unroll
            for (int k = 0; k < 4; k++) acc[i][j][k] = 0.f;

    // halo row 0 = padded position 132*tile (tile base = 132*tile + 67)
    const size_t xrow0 = ((size_t)n * NPOS_STRIDE + POS_BASE + 132 * tile) * 128;
    const __half* wbase = g_wb + (coB << 13);   // co block offset

    // ---- prologue ----
    // B(iter 0): each pair loads ONLY its own 32-row quarter (4 x 16B / thread)
#pragma unroll
    for (int k = 0; k < 4; k++) {
        const int u = pt + (k << 6);               // 0..255 within quarter
        const int r = (nw << 5) + (u >> 3), j = u & 7;
        const uint32_t doff = (uint32_t)(r * 128 + ((j ^ (r & 7)) << 4));
        CP_ASYNC16(smb + SM_B0 + doff, wbase + (r << 6) + (j << 3));
    }
    CP_COMMIT();
    // A halo: 264 rows x 256B, all threads
    for (int i = t; i < A_ROWS * 16; i += 256) {
        const int r = i >> 4, j = i & 15;
        const size_t gsrc = xrow0 + (size_t)r * 128 + (j << 3);
        const uint32_t doff = (uint32_t)(r * 256 + ((j ^ (r & 7)) << 4));
        CP_ASYNC16(smb + SM_A + doff, g_xh + gsrc);
    }
    CP_COMMIT();
    CP_WAIT0();
    __syncthreads();           // A + B0 visible to all warps

#pragma unroll 1
    for (int iter = 0; iter < 18; ++iter) {
        const int chunk = iter / 9;
        const int tap   = iter - chunk * 9;

        // own B(iter)-quarter writes landed (committed previous iter)
        CP_WAIT0();
        // partner's writes visible + partner done computing iter-1
        PAIR_BAR(1 + nw);

        if (iter < 17) {       // prefetch own quarter of B(iter+1)
            const __half* src = wbase + ((iter + 1) << 14);
            const uint32_t bdst = smb + (((iter + 1) & 1) ? SM_B1 : SM_B0);
#pragma unroll
            for (int k = 0; k < 4; k++) {
                const int u = pt + (k << 6);
                const int r = (nw << 5) + (u >> 3), j = u & 7;
                const uint32_t doff = (uint32_t)(r * 128 + ((j ^ (r & 7)) << 4));
                CP_ASYNC16(bdst + doff, src + (r << 6) + (j << 3));
            }
            CP_COMMIT();
        }

        // ---- compute tap/chunk ----
        const int s = (tap / 3 - 1) * 66 + (tap % 3 - 1);
        const int aRow0 = mw * 66 + s + 67 + rA;
        const uint32_t aBase = smb + SM_A + (uint32_t)aRow0 * 256;
        const uint32_t aXorM = (uint32_t)(aRow0 & 7);
        const uint32_t bBase = smb + ((iter & 1) ? SM_B1 : SM_B0) + bRowOff;
        const int cbase = chunk << 3;

#pragma unroll
        for (int ks = 0; ks < 4; ks++) {
            uint32_t bf[4][2];
#pragma unroll
            for (int pr = 0; pr < 2; pr++) {
                const uint32_t addr = bBase + pr * 2048 +
                    (((uint32_t)(2 * ks + cB) ^ bXorM) << 4);
                ldsm_x4(bf[pr * 2][0], bf[pr * 2][1],
                        bf[pr * 2 + 1][0], bf[pr * 2 + 1][1], addr);
            }
            uint32_t af[4][4];
#pragma unroll
            for (int mt = 0; mt < 4; mt++) {
                const uint32_t addr = aBase + mt * 4096 +
                    (((uint32_t)(cbase + 2 * ks + cA) ^ aXorM) << 4);
                ldsm_x4(af[mt][0], af[mt][1], af[mt][2], af[mt][3], addr);
            }
#pragma unroll
            for (int mt = 0; mt < 4; mt++)
#pragma unroll
                for (int nt = 0; nt < 4; nt++)
                    mma_f16(acc[mt][nt], af[mt], bf[nt][0], bf[nt][1]);
        }
    }

    // ---- epilogue: acc -> smem D [co][132] -> float4 coalesced gmem stores ----
    __syncthreads();           // all pairs done; A region becomes D
    float* D = (float*)sm;
    const int gRow = lane >> 2;
    const int gCol = (lane & 3) * 2;
#pragma unroll
    for (int mt = 0; mt < 4; mt++) {
#pragma unroll
        for (int nt = 0; nt < 4; nt++) {
            const int pl  = mw * 64 + mt * 16 + gRow;
            const int col = nw * 32 + nt * 8 + gCol;
            D[col * 132 + pl]           = acc[mt][nt][0];
            D[(col + 1) * 132 + pl]     = acc[mt][nt][1];
            D[col * 132 + pl + 8]       = acc[mt][nt][2];
            D[(col + 1) * 132 + pl + 8] = acc[mt][nt][3];
        }
    }
    __syncthreads();

    // float4: p_l = 4*p4 never straddles a 64-col segment (4 | 64)
    float* obase = out + (((size_t)n * 256 + coB * 128) << 12) + (2 * tile << 6);
    for (int i = t; i < 128 * 32; i += 256) {
        const int co_l = i >> 5, p4 = i & 31;
        const float4 v = *(const float4*)&D[co_l * 132 + 4 * p4];
        // p4 0..15 -> row 2*tile cols 4*p4; p4 16..31 -> row 2*tile+1
        *(float4*)&obase[((size_t)co_l << 12) + 4 * p4] = v;   // contiguous rows
    }
}

// ------------------------------- launcher ------------------------------------
extern "C" void kernel_launch(void* const* d_in, const int* in_sizes, int n_in,
                              void* d_out, int out_size) {
    const float* x = (const float*)d_in[0];
    const float* w = (const float*)d_in[1];
    float* out = (float*)d_out;

    cudaFuncSetAttribute(bconv_hmma, cudaFuncAttributeMaxDynamicSharedMemorySize,
                         SM_TOTAL);

    prep_all<<<2304, 256>>>(x, w);
    bconv_hmma<<<dim3(N_TILES, 2, 32), 256, SM_TOTAL>>>(out);
}